// round 14
// baseline (speedup 1.0000x reference)
#include <cuda_runtime.h>
#include <math.h>
#include <stdint.h>

#define LSEQ 2048
#define HD   512
#define BSZ  16

// ------------- device scratch (static; no runtime allocation) -------------
__device__ __align__(16) float d_P [11 * 4096];
__device__ __align__(16) float d_PT[11 * 4096];
__device__ __align__(16) float d_Bbar[64];
__device__ __align__(16) float d_W0 [64 * 64];
__device__ __align__(16) float d_Vr0[64 * 64];
__device__ __align__(16) float d_W[LSEQ * 64];    // w[s][n]
__device__ __align__(16) float d_V[LSEQ * 64];    // v[t][n] = C Abar^{L-1-t}

// =============== packed f32x2 helpers ===============
__device__ __forceinline__ uint64_t dup2(float x) {
    uint64_t r; uint32_t u = __float_as_uint(x);
    asm("mov.b64 %0, {%1, %1};" : "=l"(r) : "r"(u));
    return r;
}
__device__ __forceinline__ void fma2(uint64_t& d, uint64_t a, uint64_t b) {
    asm("fma.rn.f32x2 %0, %1, %2, %0;" : "+l"(d) : "l"(a), "l"(b));
}
__device__ __forceinline__ void add2(uint64_t& d, uint64_t a) {
    asm("add.rn.f32x2 %0, %0, %1;" : "+l"(d) : "l"(a));
}
__device__ __forceinline__ float2 un2(uint64_t v) {
    float2 r;
    asm("mov.b64 {%0, %1}, %2;" : "=f"(r.x), "=f"(r.y) : "l"(v));
    return r;
}
__device__ __forceinline__ void cpa16(uint32_t dst, const void* src) {
    asm volatile("cp.async.ca.shared.global [%0], [%1], 16;"
                 :: "r"(dst), "l"(__cvta_generic_to_global(src)));
}
__device__ __forceinline__ void cpa_commit() {
    asm volatile("cp.async.commit_group;");
}
__device__ __forceinline__ void cpa_wait0() {
    asm volatile("cp.async.wait_group 0;" ::: "memory");
}

// =============== setup matmul: 256 threads, 4x4 tiles, f32x2 inner loop ===============
// Same thread mapping / epilogue as the proven R6-R10 mm64T; only the k-loop
// math is packed (2x fewer FFMA issue slots).
__device__ __forceinline__ void mm64T(const float* __restrict__ AT, const float* __restrict__ B,
                                      float* __restrict__ C, float* __restrict__ CT,
                                      int tid, int mode, float scale) {
    int tx = tid & 15, ty = tid >> 4;
    int j0 = tx << 2, i0 = ty << 2;
    uint64_t acc[4][2];
#pragma unroll
    for (int a = 0; a < 4; a++) { acc[a][0] = 0ull; acc[a][1] = 0ull; }
#pragma unroll 8
    for (int k = 0; k < 64; k++) {
        float4 av = *(const float4*)(AT + k * 64 + i0);
        ulonglong2 bv = *(const ulonglong2*)(B + k * 64 + j0);
#pragma unroll
        for (int a = 0; a < 4; a++) {
            uint64_t ad = dup2((&av.x)[a]);
            fma2(acc[a][0], ad, bv.x);
            fma2(acc[a][1], ad, bv.y);
        }
    }
    float o[4][4];
#pragma unroll
    for (int a = 0; a < 4; a++) {
        float2 p0 = un2(acc[a][0]);
        float2 p1 = un2(acc[a][1]);
        o[a][0] = p0.x; o[a][1] = p0.y; o[a][2] = p1.x; o[a][3] = p1.y;
        if (mode == 1) {
#pragma unroll
            for (int q = 0; q < 4; q++)
                o[a][q] = o[a][q] * scale + ((i0 + a) == (j0 + q) ? 1.f : 0.f);
        }
        float4 ov; ov.x = o[a][0]; ov.y = o[a][1]; ov.z = o[a][2]; ov.w = o[a][3];
        *(float4*)(C + (i0 + a) * 64 + j0) = ov;
    }
#pragma unroll
    for (int q = 0; q < 4; q++) {
        float4 ov; ov.x = o[0][q]; ov.y = o[1][q]; ov.z = o[2][q]; ov.w = o[3][q];
        *(float4*)(CT + (j0 + q) * 64 + i0) = ov;
    }
}

__global__ void __launch_bounds__(256, 1)
setup_kernel(const float* __restrict__ B_in, const float* __restrict__ logdt) {
    extern __shared__ float sm[];
    float* As  = sm;
    float* Xs  = sm + 4096;
    float* XsT = sm + 8192;
    float* R0  = sm + 12288;
    float* R0T = sm + 16384;
    float* R1  = sm + 20480;
    float* R1T = sm + 24576;
    __shared__ float colsum[64], rhs[64], bbsh[64], bsh[64];
    __shared__ int s_sh;
    int tid = threadIdx.x;

    double dt = exp((double)logdt[0]);
    for (int e = tid; e < 4096; e += 256) {
        int i = e >> 6, j = e & 63;
        float a = 0.f, x = 0.f;
        if (j <= i) {
            double pij = sqrt((1.0 + 2.0 * i) * (1.0 + 2.0 * j));
            double av = pij - (i == j ? (double)i : 0.0);
            a = (float)(-av);
            x = (float)(-av * dt);
        }
        As[e] = a; Xs[e] = x;
        XsT[(j << 6) + i] = x;
    }
    if (tid < 64) bsh[tid] = B_in[tid];
    __syncthreads();
    if (tid < 64) {
        float ssum = 0.f;
        for (int i = tid; i < 64; i++) ssum += fabsf(Xs[i * 64 + tid]);
        colsum[tid] = ssum;
    }
    __syncthreads();
    if (tid == 0) {
        float mx = 0.f;
        for (int j = 0; j < 64; j++) mx = fmaxf(mx, colsum[j]);
        int s = 0; float v = mx;
        while (v > 2.0f && s < 30) { v *= 0.5f; s++; }   // theta = 2 (deg-12 trunc ~1.3e-6)
        s_sh = s;
    }
    __syncthreads();
    int s = s_sh;
    float scale = ldexpf(1.0f, -s);
    for (int e = tid; e < 4096; e += 256) { Xs[e] *= scale; XsT[e] *= scale; }
    __syncthreads();

    // Taylor deg-12 Horner: R = I + X/12; for k=11..1: R = I + (X*R)/k
    for (int e = tid; e < 4096; e += 256) {
        int i = e >> 6, j = e & 63;
        float d = (i == j) ? 1.f : 0.f;
        R0[e]  = Xs[e]  * (1.f / 12.f) + d;
        R0T[e] = XsT[e] * (1.f / 12.f) + d;
    }
    __syncthreads();
    float *cur = R0, *curT = R0T, *nxt = R1, *nxtT = R1T;
    for (int k = 11; k >= 1; k--) {
        mm64T(XsT, cur, nxt, nxtT, tid, 1, 1.f / (float)k);
        __syncthreads();
        float* t;
        t = cur; cur = nxt; nxt = t;
        t = curT; curT = nxtT; nxtT = t;
    }
    for (int q = 0; q < s; q++) {
        mm64T(curT, cur, nxt, nxtT, tid, 0, 0.f);
        __syncthreads();
        float* t;
        t = cur; cur = nxt; nxt = t;
        t = curT; curT = nxtT; nxtT = t;
    }
    if (tid < 64) {
        float acc = 0.f;
        for (int j = 0; j < 64; j++) {
            float p = cur[tid * 64 + j] - (tid == j ? 1.f : 0.f);
            acc = fmaf(p, bsh[j], acc);
        }
        rhs[tid] = acc;
    }
    __syncthreads();
    for (int e = tid; e < 4096; e += 256) { d_P[e] = cur[e]; d_PT[e] = curT[e]; }
    for (int k = 1; k < 11; k++) {
        mm64T(curT, cur, nxt, nxtT, tid, 0, 0.f);
        __syncthreads();
        for (int e = tid; e < 4096; e += 256) {
            d_P [k * 4096 + e] = nxt[e];
            d_PT[k * 4096 + e] = nxtT[e];
        }
        float* t;
        t = cur; cur = nxt; nxt = t;
        t = curT; curT = nxtT; nxtT = t;
        __syncthreads();
    }
    float accv = (tid < 64) ? rhs[tid] : 0.f;
    for (int j = 0; j < 64; j++) {
        if (tid == j) bbsh[j] = accv / As[j * 64 + j];
        __syncthreads();
        if (tid < 64 && tid > j) accv = fmaf(-As[tid * 64 + j], bbsh[j], accv);
        __syncthreads();
    }
    if (tid < 64) d_Bbar[tid] = bbsh[tid];
}

// =============== stage A: Krylov doubling for first 64 w / vrev ===============
__global__ void __launch_bounds__(256, 1)
stageA_kernel(const float* __restrict__ C_in) {
    __shared__ float M[4096];
    __shared__ float Pb[4096];
    int tid = threadIdx.x;
    int isW = (blockIdx.x == 0);
    if (tid < 64) M[tid] = isW ? d_Bbar[tid] : C_in[tid];
    for (int k = 0; k < 6; k++) {
        const float* src = (isW ? d_PT : d_P) + k * 4096;
        __syncthreads();
        for (int f = tid; f < 1024; f += 256)
            ((float4*)Pb)[f] = __ldg((const float4*)src + f);
        __syncthreads();
        int half = 1 << k;
        for (int idx = tid; idx < half * 16; idx += 256) {
            int row = idx >> 4, n0 = (idx & 15) << 2;
            float4 acc = make_float4(0.f, 0.f, 0.f, 0.f);
            for (int m = 0; m < 64; m++) {
                float w = M[row * 64 + m];
                float4 p = *(const float4*)(Pb + m * 64 + n0);
                acc.x = fmaf(w, p.x, acc.x);
                acc.y = fmaf(w, p.y, acc.y);
                acc.z = fmaf(w, p.z, acc.z);
                acc.w = fmaf(w, p.w, acc.w);
            }
            *(float4*)(M + (half + row) * 64 + n0) = acc;
        }
    }
    __syncthreads();
    float* dst = isW ? d_W0 : d_Vr0;
    for (int f = tid; f < 1024; f += 256) ((float4*)dst)[f] = ((const float4*)M)[f];
}

// =============== chunk kernel ===============
__device__ __forceinline__ void mmg(const float* __restrict__ A, const float* __restrict__ B,
                                    float* __restrict__ out, int row0, int rowstep, int tid) {
    int tx = tid & 15, ty = tid >> 4;
    int j0 = tx << 2, i0 = ty << 2;
    float acc[4][4];
#pragma unroll
    for (int a = 0; a < 4; a++)
#pragma unroll
        for (int q = 0; q < 4; q++) acc[a][q] = 0.f;
#pragma unroll 8
    for (int k = 0; k < 64; k++) {
        float a0 = A[(i0 + 0) * 64 + k];
        float a1 = A[(i0 + 1) * 64 + k];
        float a2 = A[(i0 + 2) * 64 + k];
        float a3 = A[(i0 + 3) * 64 + k];
        float4 bv = *(const float4*)(B + k * 64 + j0);
        acc[0][0] = fmaf(a0, bv.x, acc[0][0]); acc[0][1] = fmaf(a0, bv.y, acc[0][1]);
        acc[0][2] = fmaf(a0, bv.z, acc[0][2]); acc[0][3] = fmaf(a0, bv.w, acc[0][3]);
        acc[1][0] = fmaf(a1, bv.x, acc[1][0]); acc[1][1] = fmaf(a1, bv.y, acc[1][1]);
        acc[1][2] = fmaf(a1, bv.z, acc[1][2]); acc[1][3] = fmaf(a1, bv.w, acc[1][3]);
        acc[2][0] = fmaf(a2, bv.x, acc[2][0]); acc[2][1] = fmaf(a2, bv.y, acc[2][1]);
        acc[2][2] = fmaf(a2, bv.z, acc[2][2]); acc[2][3] = fmaf(a2, bv.w, acc[2][3]);
        acc[3][0] = fmaf(a3, bv.x, acc[3][0]); acc[3][1] = fmaf(a3, bv.y, acc[3][1]);
        acc[3][2] = fmaf(a3, bv.z, acc[3][2]); acc[3][3] = fmaf(a3, bv.w, acc[3][3]);
    }
#pragma unroll
    for (int a = 0; a < 4; a++) {
        float4 o; o.x = acc[a][0]; o.y = acc[a][1]; o.z = acc[a][2]; o.w = acc[a][3];
        *(float4*)(out + (size_t)(row0 + rowstep * (i0 + a)) * 64 + j0) = o;
    }
}

__global__ void __launch_bounds__(256, 1)
chunk_kernel() {
    extern __shared__ float cs[];
    float* W0s  = cs;
    float* Vr0s = cs + 4096;
    float* Qa   = cs + 8192;
    float* Qb   = cs + 12288;
    float* QT   = cs + 16384;
    float* Pb   = cs + 20480;
    int tid = threadIdx.x;
    int c = blockIdx.x;

    for (int f = tid; f < 1024; f += 256) {
        ((float4*)W0s)[f]  = __ldg((const float4*)d_W0 + f);
        ((float4*)Vr0s)[f] = __ldg((const float4*)d_Vr0 + f);
    }
    __syncthreads();

    if (c == 0) {
        for (int f = tid; f < 1024; f += 256) ((float4*)d_W)[f] = ((const float4*)W0s)[f];
        for (int e = tid; e < 4096; e += 256) {
            int r = e >> 6, n = e & 63;
            d_V[(size_t)(2047 - r) * 64 + n] = Vr0s[e];
        }
        return;
    }

    int bits = c;
    int k0 = __ffs(bits) - 1; bits &= bits - 1;
    for (int f = tid; f < 1024; f += 256)
        ((float4*)Qa)[f] = __ldg((const float4*)(d_P + (6 + k0) * 4096) + f);
    float *qcur = Qa, *qnxt = Qb;
    while (bits) {
        int k = __ffs(bits) - 1; bits &= bits - 1;
        __syncthreads();
        for (int f = tid; f < 1024; f += 256)
            ((float4*)Pb)[f] = __ldg((const float4*)(d_P + (6 + k) * 4096) + f);
        __syncthreads();
        mmg(qcur, Pb, qnxt, 0, 1, tid);
        float* t = qcur; qcur = qnxt; qnxt = t;
    }
    __syncthreads();
    for (int e = tid; e < 4096; e += 256) {
        int i = e >> 6, j = e & 63;
        QT[j * 64 + i] = qcur[e];
    }
    __syncthreads();
    mmg(W0s, QT, d_W, 64 * c, 1, tid);
    mmg(Vr0s, qcur, d_V, 2047 - 64 * c, -1, tid);
}

// =============== main fused chunked-scan kernel (EXACT R10 version) ===============
// 512 threads, 4 roles x 128 threads, 8i x 4h register tiles, f32x2 math.
//   role 0: YA = V*Xcur          (K=64)  -> Yb (smem)
//   role 1: YB = Tz*U + D*U      (K=64)  -> regs; then y = YA+YB -> gmem
//   role 2: Xnxt = Xcur + sum_{j<32}  W^T U  -> Xnxt (smem)
//   role 3: partial sum_{j>=32} W^T U -> regs; then Xnxt += partial
// U/W double-buffered via cp.async; V double-buffered via reg prefetch + transposed STS.
__device__ __forceinline__ void g8x4(uint64_t acc[8][2], const float* __restrict__ A,
                                     const float* __restrict__ B, int k, int r0, int h0) {
    const float* ar = A + k * 64 + r0;
    float4 a03 = *(const float4*)ar;
    float4 a47 = *(const float4*)(ar + 4);
    ulonglong2 bv = *(const ulonglong2*)(B + k * 64 + h0);
    float av[8] = {a03.x, a03.y, a03.z, a03.w, a47.x, a47.y, a47.z, a47.w};
#pragma unroll
    for (int ai = 0; ai < 8; ai++) {
        uint64_t ad = dup2(av[ai]);
        fma2(acc[ai][0], ad, bv.x);
        fma2(acc[ai][1], ad, bv.y);
    }
}

__global__ void __launch_bounds__(512, 1)
main_kernel(const float* __restrict__ u, const float* __restrict__ Dp, float* __restrict__ y) {
    extern __shared__ float sm[];
    float* Us0 = sm;            // [64][64] u tile, buffer 0
    float* Us1 = sm + 4096;
    float* Ws0 = sm + 8192;     // [64][64] W tile
    float* Ws1 = sm + 12288;
    float* Vt0 = sm + 16384;    // [64][64] V transposed [n][i]
    float* Vt1 = sm + 20480;
    float* Tz  = sm + 24576;    // [64][64] TzT[j][i]
    float* Xb0 = sm + 28672;    // [64][64] state ping
    float* Xb1 = sm + 32768;    // [64][64] state pong
    float* Yb_ = sm + 36864;    // [64][64] Y partial

    int tid = threadIdx.x;
    int b = blockIdx.x >> 3;
    int habs = (blockIdx.x & 7) << 6;
    float Dv = Dp[0];
    uint64_t dv2 = dup2(Dv);

    uint32_t smem_u32 = (uint32_t)__cvta_generic_to_shared(sm);

    int role = tid >> 7;          // 0..3
    int t7 = tid & 127;
    int r0 = (t7 >> 4) << 3;      // i/n tile base: 0,8,...,56
    int h0 = (t7 & 15) << 2;      // h base: 0,4,...,60

    // staging coords
    int vii = tid & 63, vng = tid >> 6;   // V prefetch: 8 n per thread (8 groups)
    int n0v = vng << 3;

    const float* ub = u + (size_t)b * LSEQ * HD + habs;
    float*       yb = y + (size_t)b * LSEQ * HD + habs;

    // ---- zero X ping, stage chunk 0 (synchronous) ----
    for (int e = tid; e < 4096; e += 512) Xb0[e] = 0.f;
    for (int f = tid; f < 1024; f += 512) {
        int j = f >> 4, q = f & 15;
        ((float4*)Us0)[(j << 4) + q] = __ldg((const float4*)(ub + (size_t)j * HD) + q);
        ((float4*)Ws0)[f] = __ldg((const float4*)d_W + f);
    }
    {
        const float* Vrow = d_V + (size_t)vii * 64 + n0v;
#pragma unroll
        for (int q2 = 0; q2 < 2; q2++) {
            float4 v = *(const float4*)(Vrow + (q2 << 2));
            int nn = n0v + (q2 << 2);
            Vt0[(nn + 0) * 64 + vii] = v.x;
            Vt0[(nn + 1) * 64 + vii] = v.y;
            Vt0[(nn + 2) * 64 + vii] = v.z;
            Vt0[(nn + 3) * 64 + vii] = v.w;
        }
    }
    __syncthreads();

    // ---- one-time Toeplitz: Tz[j][i] = dot(v_i, w_j) masked i>=j ----
    {
        int jj = tid >> 3;
        int i0t = (tid & 7) << 3;
        float ta[8];
#pragma unroll
        for (int q = 0; q < 8; q++) ta[q] = 0.f;
#pragma unroll 4
        for (int n = 0; n < 64; n++) {
            float w = Ws0[jj * 64 + n];
            const float* vr = Vt0 + n * 64 + i0t;
            float4 v0 = *(const float4*)(vr);
            float4 v1 = *(const float4*)(vr + 4);
#pragma unroll
            for (int q = 0; q < 4; q++) {
                ta[q]     = fmaf(w, (&v0.x)[q], ta[q]);
                ta[4 + q] = fmaf(w, (&v1.x)[q], ta[4 + q]);
            }
        }
#pragma unroll
        for (int q = 0; q < 8; q++)
            Tz[jj * 64 + i0t + q] = (i0t + q >= jj) ? ta[q] : 0.f;
    }
    __syncthreads();

    float* Xc = Xb0;
    float* Xn = Xb1;

    for (int c = 0; c < 32; c++) {
        int p = c & 1;
        int tb = c << 6;
        const float* Uc = p ? Us1 : Us0;
        const float* Wc = p ? Ws1 : Ws0;
        const float* Vc = p ? Vt1 : Vt0;
        uint32_t uAlt = smem_u32 + (p ? 0u : 4096u * 4u);
        uint32_t wAlt = smem_u32 + (p ? 8192u * 4u : 12288u * 4u);
        float*   vAlt = p ? Vt0 : Vt1;

        // ---- async prefetch next chunk: U and W via cp.async ----
        float4 pv[2];
        if (c < 31) {
            int tbn = tb + 64;
#pragma unroll
            for (int it = 0; it < 2; it++) {
                int f = (it << 9) + tid;
                int j = f >> 4, q = f & 15;
                cpa16(uAlt + (uint32_t)((j << 6) + (q << 2)) * 4u,
                      ub + (size_t)(tbn + j) * HD + (q << 2));
                cpa16(wAlt + (uint32_t)((j << 6) + (q << 2)) * 4u,
                      d_W + (size_t)(tbn + j) * 64 + (q << 2));
            }
            cpa_commit();
            const float* Vrow = d_V + (size_t)(tbn + vii) * 64 + n0v;
#pragma unroll
            for (int q2 = 0; q2 < 2; q2++) pv[q2] = *(const float4*)(Vrow + (q2 << 2));
        }

        // ---- compute role partials ----
        uint64_t acc[8][2];
#pragma unroll
        for (int ai = 0; ai < 8; ai++) { acc[ai][0] = 0ull; acc[ai][1] = 0ull; }

        if (role == 0) {
#pragma unroll 4
            for (int n = 0; n < 64; n++) g8x4(acc, Vc, Xc, n, r0, h0);
#pragma unroll
            for (int ai = 0; ai < 8; ai++) {
                ulonglong2 o; o.x = acc[ai][0]; o.y = acc[ai][1];
                *(ulonglong2*)(Yb_ + (r0 + ai) * 64 + h0) = o;
            }
        } else if (role == 1) {
#pragma unroll 4
            for (int j = 0; j < 64; j++) g8x4(acc, Tz, Uc, j, r0, h0);
#pragma unroll
            for (int ai = 0; ai < 8; ai++) {
                ulonglong2 uv = *(const ulonglong2*)(Uc + (r0 + ai) * 64 + h0);
                fma2(acc[ai][0], dv2, uv.x);
                fma2(acc[ai][1], dv2, uv.y);
            }
        } else if (role == 2) {
#pragma unroll 4
            for (int j = 0; j < 32; j++) g8x4(acc, Wc, Uc, j, r0, h0);
#pragma unroll
            for (int ai = 0; ai < 8; ai++) {
                ulonglong2 xv = *(const ulonglong2*)(Xc + (r0 + ai) * 64 + h0);
                add2(acc[ai][0], xv.x);
                add2(acc[ai][1], xv.y);
                ulonglong2 o; o.x = acc[ai][0]; o.y = acc[ai][1];
                *(ulonglong2*)(Xn + (r0 + ai) * 64 + h0) = o;
            }
        } else {
#pragma unroll 4
            for (int j = 32; j < 64; j++) g8x4(acc, Wc, Uc, j, r0, h0);
        }

        // ---- V prefetch STS into alt buffer (all threads) ----
        if (c < 31) {
#pragma unroll
            for (int q2 = 0; q2 < 2; q2++) {
                int nn = n0v + (q2 << 2);
                vAlt[(nn + 0) * 64 + vii] = pv[q2].x;
                vAlt[(nn + 1) * 64 + vii] = pv[q2].y;
                vAlt[(nn + 2) * 64 + vii] = pv[q2].z;
                vAlt[(nn + 3) * 64 + vii] = pv[q2].w;
            }
        }
        __syncthreads();   // Yb + Xn(partial A) visible

        if (role == 1) {
#pragma unroll
            for (int ai = 0; ai < 8; ai++) {
                ulonglong2 p1 = *(const ulonglong2*)(Yb_ + (r0 + ai) * 64 + h0);
                add2(acc[ai][0], p1.x);
                add2(acc[ai][1], p1.y);
                ulonglong2 o; o.x = acc[ai][0]; o.y = acc[ai][1];
                *(ulonglong2*)(yb + (size_t)(tb + r0 + ai) * HD + h0) = o;
            }
        } else if (role == 3) {
#pragma unroll
            for (int ai = 0; ai < 8; ai++) {
                float* xrow = Xn + (r0 + ai) * 64 + h0;
                ulonglong2 xv = *(const ulonglong2*)xrow;
                add2(acc[ai][0], xv.x);
                add2(acc[ai][1], xv.y);
                ulonglong2 o; o.x = acc[ai][0]; o.y = acc[ai][1];
                *(ulonglong2*)xrow = o;
            }
        }

        cpa_wait0();
        __syncthreads();   // Xn final, new tiles landed

        float* t = Xc; Xc = Xn; Xn = t;
    }
}

extern "C" void kernel_launch(void* const* d_in, const int* in_sizes, int n_in,
                              void* d_out, int out_size) {
    const float* u      = (const float*)d_in[0];
    const float* B_ssm  = (const float*)d_in[1];
    const float* C_ssm  = (const float*)d_in[2];
    const float* D_skip = (const float*)d_in[3];
    const float* log_dt = (const float*)d_in[4];
    float* y = (float*)d_out;

    cudaFuncSetAttribute(setup_kernel, cudaFuncAttributeMaxDynamicSharedMemorySize, 114688);
    cudaFuncSetAttribute(chunk_kernel, cudaFuncAttributeMaxDynamicSharedMemorySize, 98304);
    cudaFuncSetAttribute(main_kernel,  cudaFuncAttributeMaxDynamicSharedMemorySize, 163840);

    setup_kernel<<<1, 256, 114688>>>(B_ssm, log_dt);
    stageA_kernel<<<2, 256>>>(C_ssm);
    chunk_kernel<<<32, 256, 98304>>>();
    main_kernel<<<BSZ * 8, 512, 163840>>>(u, D_skip, y);
}

// round 16
// speedup vs baseline: 1.8534x; 1.8534x over previous
#include <cuda_runtime.h>
#include <cuda_bf16.h>
#include <math.h>
#include <stdint.h>

#define LSEQ 2048
#define HD   512
#define BSZ  16

__device__ __align__(16) float d_P [11 * 4096];
__device__ __align__(16) float d_PT[11 * 4096];
__device__ __align__(16) float d_Bbar[64];
__device__ __align__(16) float d_W0 [64 * 64];
__device__ __align__(16) float d_Vr0[64 * 64];
__device__ __align__(16) float d_W[LSEQ * 64];
__device__ __align__(16) float d_V[LSEQ * 64];

__device__ __forceinline__ uint64_t dup2(float x) {
    uint64_t r; uint32_t u = __float_as_uint(x);
    asm("mov.b64 %0, {%1, %1};" : "=l"(r) : "r"(u));
    return r;
}
__device__ __forceinline__ void fma2(uint64_t& d, uint64_t a, uint64_t b) {
    asm("fma.rn.f32x2 %0, %1, %2, %0;" : "+l"(d) : "l"(a), "l"(b));
}
__device__ __forceinline__ float2 un2(uint64_t v) {
    float2 r;
    asm("mov.b64 {%0, %1}, %2;" : "=f"(r.x), "=f"(r.y) : "l"(v));
    return r;
}
__device__ __forceinline__ void split2(float x, __nv_bfloat16& h, __nv_bfloat16& l) {
    h = __float2bfloat16(x);
    l = __float2bfloat16(x - __bfloat162float(h));
}

// =============== setup (R13, proven) ===============
__device__ __forceinline__ void mm64T(const float* __restrict__ AT, const float* __restrict__ B,
                                      float* __restrict__ C, float* __restrict__ CT,
                                      int tid, int mode, float scale) {
    int tx = tid & 15, ty = tid >> 4;
    int j0 = tx << 2, i0 = ty << 2;
    uint64_t acc[4][2];
#pragma unroll
    for (int a = 0; a < 4; a++) { acc[a][0] = 0ull; acc[a][1] = 0ull; }
#pragma unroll 8
    for (int k = 0; k < 64; k++) {
        float4 av = *(const float4*)(AT + k * 64 + i0);
        ulonglong2 bv = *(const ulonglong2*)(B + k * 64 + j0);
#pragma unroll
        for (int a = 0; a < 4; a++) {
            uint64_t ad = dup2((&av.x)[a]);
            fma2(acc[a][0], ad, bv.x);
            fma2(acc[a][1], ad, bv.y);
        }
    }
    float o[4][4];
#pragma unroll
    for (int a = 0; a < 4; a++) {
        float2 p0 = un2(acc[a][0]);
        float2 p1 = un2(acc[a][1]);
        o[a][0] = p0.x; o[a][1] = p0.y; o[a][2] = p1.x; o[a][3] = p1.y;
        if (mode == 1) {
#pragma unroll
            for (int q = 0; q < 4; q++)
                o[a][q] = o[a][q] * scale + ((i0 + a) == (j0 + q) ? 1.f : 0.f);
        }
        float4 ov; ov.x = o[a][0]; ov.y = o[a][1]; ov.z = o[a][2]; ov.w = o[a][3];
        *(float4*)(C + (i0 + a) * 64 + j0) = ov;
    }
#pragma unroll
    for (int q = 0; q < 4; q++) {
        float4 ov; ov.x = o[0][q]; ov.y = o[1][q]; ov.z = o[2][q]; ov.w = o[3][q];
        *(float4*)(CT + (j0 + q) * 64 + i0) = ov;
    }
}

__global__ void __launch_bounds__(256, 1)
setup_kernel(const float* __restrict__ B_in, const float* __restrict__ logdt) {
    extern __shared__ float sm[];
    float* As = sm;
    float* Xs = sm + 4096;
    float* XsT = sm + 8192;
    float* R0 = sm + 12288;
    float* R0T = sm + 16384;
    float* R1 = sm + 20480;
    float* R1T = sm + 24576;
    __shared__ float colsum[64], rhs[64], bbsh[64], bsh[64];
    __shared__ int s_sh;
    int tid = threadIdx.x;
    double dt = exp((double)logdt[0]);
    for (int e = tid; e < 4096; e += 256) {
        int i = e >> 6, j = e & 63;
        float a = 0.f, x = 0.f;
        if (j <= i) {
            double pij = sqrt((1.0 + 2.0 * i) * (1.0 + 2.0 * j));
            double av = pij - (i == j ? (double)i : 0.0);
            a = (float)(-av); x = (float)(-av * dt);
        }
        As[e] = a; Xs[e] = x; XsT[(j << 6) + i] = x;
    }
    if (tid < 64) bsh[tid] = B_in[tid];
    __syncthreads();
    if (tid < 64) {
        float ssum = 0.f;
        for (int i = tid; i < 64; i++) ssum += fabsf(Xs[i * 64 + tid]);
        colsum[tid] = ssum;
    }
    __syncthreads();
    if (tid == 0) {
        float mx = 0.f;
        for (int j = 0; j < 64; j++) mx = fmaxf(mx, colsum[j]);
        int s = 0; float v = mx;
        while (v > 2.0f && s < 30) { v *= 0.5f; s++; }
        s_sh = s;
    }
    __syncthreads();
    int s = s_sh;
    float scale = ldexpf(1.0f, -s);
    for (int e = tid; e < 4096; e += 256) { Xs[e] *= scale; XsT[e] *= scale; }
    __syncthreads();
    for (int e = tid; e < 4096; e += 256) {
        int i = e >> 6, j = e & 63;
        float d = (i == j) ? 1.f : 0.f;
        R0[e] = Xs[e] * (1.f / 12.f) + d;
        R0T[e] = XsT[e] * (1.f / 12.f) + d;
    }
    __syncthreads();
    float *cur = R0, *curT = R0T, *nxt = R1, *nxtT = R1T;
    for (int k = 11; k >= 1; k--) {
        mm64T(XsT, cur, nxt, nxtT, tid, 1, 1.f / (float)k);
        __syncthreads();
        float* t;
        t = cur; cur = nxt; nxt = t;
        t = curT; curT = nxtT; nxtT = t;
    }
    for (int q = 0; q < s; q++) {
        mm64T(curT, cur, nxt, nxtT, tid, 0, 0.f);
        __syncthreads();
        float* t;
        t = cur; cur = nxt; nxt = t;
        t = curT; curT = nxtT; nxtT = t;
    }
    if (tid < 64) {
        float acc = 0.f;
        for (int j = 0; j < 64; j++) {
            float p = cur[tid * 64 + j] - (tid == j ? 1.f : 0.f);
            acc = fmaf(p, bsh[j], acc);
        }
        rhs[tid] = acc;
    }
    __syncthreads();
    for (int e = tid; e < 4096; e += 256) { d_P[e] = cur[e]; d_PT[e] = curT[e]; }
    for (int k = 1; k < 11; k++) {
        mm64T(curT, cur, nxt, nxtT, tid, 0, 0.f);
        __syncthreads();
        for (int e = tid; e < 4096; e += 256) {
            d_P[k * 4096 + e] = nxt[e];
            d_PT[k * 4096 + e] = nxtT[e];
        }
        float* t;
        t = cur; cur = nxt; nxt = t;
        t = curT; curT = nxtT; nxtT = t;
        __syncthreads();
    }
    float accv = (tid < 64) ? rhs[tid] : 0.f;
    for (int j = 0; j < 64; j++) {
        if (tid == j) bbsh[j] = accv / As[j * 64 + j];
        __syncthreads();
        if (tid < 64 && tid > j) accv = fmaf(-As[tid * 64 + j], bbsh[j], accv);
        __syncthreads();
    }
    if (tid < 64) d_Bbar[tid] = bbsh[tid];
}

__global__ void __launch_bounds__(256, 1)
stageA_kernel(const float* __restrict__ C_in) {
    __shared__ float M[4096];
    __shared__ float Pb[4096];
    int tid = threadIdx.x;
    int isW = (blockIdx.x == 0);
    if (tid < 64) M[tid] = isW ? d_Bbar[tid] : C_in[tid];
    for (int k = 0; k < 6; k++) {
        const float* src = (isW ? d_PT : d_P) + k * 4096;
        __syncthreads();
        for (int f = tid; f < 1024; f += 256)
            ((float4*)Pb)[f] = __ldg((const float4*)src + f);
        __syncthreads();
        int half = 1 << k;
        for (int idx = tid; idx < half * 16; idx += 256) {
            int row = idx >> 4, n0 = (idx & 15) << 2;
            float4 acc = make_float4(0.f, 0.f, 0.f, 0.f);
            for (int m = 0; m < 64; m++) {
                float w = M[row * 64 + m];
                float4 p = *(const float4*)(Pb + m * 64 + n0);
                acc.x = fmaf(w, p.x, acc.x);
                acc.y = fmaf(w, p.y, acc.y);
                acc.z = fmaf(w, p.z, acc.z);
                acc.w = fmaf(w, p.w, acc.w);
            }
            *(float4*)(M + (half + row) * 64 + n0) = acc;
        }
    }
    __syncthreads();
    float* dst = isW ? d_W0 : d_Vr0;
    for (int f = tid; f < 1024; f += 256) ((float4*)dst)[f] = ((const float4*)M)[f];
}

__device__ __forceinline__ void mmg(const float* __restrict__ A, const float* __restrict__ B,
                                    float* __restrict__ out, int row0, int rowstep, int tid) {
    int tx = tid & 15, ty = tid >> 4;
    int j0 = tx << 2, i0 = ty << 2;
    float acc[4][4];
#pragma unroll
    for (int a = 0; a < 4; a++)
#pragma unroll
        for (int q = 0; q < 4; q++) acc[a][q] = 0.f;
#pragma unroll 8
    for (int k = 0; k < 64; k++) {
        float a0 = A[(i0 + 0) * 64 + k];
        float a1 = A[(i0 + 1) * 64 + k];
        float a2 = A[(i0 + 2) * 64 + k];
        float a3 = A[(i0 + 3) * 64 + k];
        float4 bv = *(const float4*)(B + k * 64 + j0);
        acc[0][0] = fmaf(a0, bv.x, acc[0][0]); acc[0][1] = fmaf(a0, bv.y, acc[0][1]);
        acc[0][2] = fmaf(a0, bv.z, acc[0][2]); acc[0][3] = fmaf(a0, bv.w, acc[0][3]);
        acc[1][0] = fmaf(a1, bv.x, acc[1][0]); acc[1][1] = fmaf(a1, bv.y, acc[1][1]);
        acc[1][2] = fmaf(a1, bv.z, acc[1][2]); acc[1][3] = fmaf(a1, bv.w, acc[1][3]);
        acc[2][0] = fmaf(a2, bv.x, acc[2][0]); acc[2][1] = fmaf(a2, bv.y, acc[2][1]);
        acc[2][2] = fmaf(a2, bv.z, acc[2][2]); acc[2][3] = fmaf(a2, bv.w, acc[2][3]);
        acc[3][0] = fmaf(a3, bv.x, acc[3][0]); acc[3][1] = fmaf(a3, bv.y, acc[3][1]);
        acc[3][2] = fmaf(a3, bv.z, acc[3][2]); acc[3][3] = fmaf(a3, bv.w, acc[3][3]);
    }
#pragma unroll
    for (int a = 0; a < 4; a++) {
        float4 o; o.x = acc[a][0]; o.y = acc[a][1]; o.z = acc[a][2]; o.w = acc[a][3];
        *(float4*)(out + (size_t)(row0 + rowstep * (i0 + a)) * 64 + j0) = o;
    }
}

__global__ void __launch_bounds__(256, 1)
chunk_kernel() {
    extern __shared__ float cs[];
    float* W0s = cs;
    float* Vr0s = cs + 4096;
    float* Qa = cs + 8192;
    float* Qb = cs + 12288;
    float* QT = cs + 16384;
    float* Pb = cs + 20480;
    int tid = threadIdx.x;
    int c = blockIdx.x;
    for (int f = tid; f < 1024; f += 256) {
        ((float4*)W0s)[f] = __ldg((const float4*)d_W0 + f);
        ((float4*)Vr0s)[f] = __ldg((const float4*)d_Vr0 + f);
    }
    __syncthreads();
    if (c == 0) {
        for (int f = tid; f < 1024; f += 256) ((float4*)d_W)[f] = ((const float4*)W0s)[f];
        for (int e = tid; e < 4096; e += 256) {
            int r = e >> 6, n = e & 63;
            d_V[(size_t)(2047 - r) * 64 + n] = Vr0s[e];
        }
        return;
    }
    int bits = c;
    int k0 = __ffs(bits) - 1; bits &= bits - 1;
    for (int f = tid; f < 1024; f += 256)
        ((float4*)Qa)[f] = __ldg((const float4*)(d_P + (6 + k0) * 4096) + f);
    float *qcur = Qa, *qnxt = Qb;
    while (bits) {
        int k = __ffs(bits) - 1; bits &= bits - 1;
        __syncthreads();
        for (int f = tid; f < 1024; f += 256)
            ((float4*)Pb)[f] = __ldg((const float4*)(d_P + (6 + k) * 4096) + f);
        __syncthreads();
        mmg(qcur, Pb, qnxt, 0, 1, tid);
        float* t = qcur; qcur = qnxt; qnxt = t;
    }
    __syncthreads();
    for (int e = tid; e < 4096; e += 256) {
        int i = e >> 6, j = e & 63;
        QT[j * 64 + i] = qcur[e];
    }
    __syncthreads();
    mmg(W0s, QT, d_W, 64 * c, 1, tid);
    mmg(Vr0s, qcur, d_V, 2047 - 64 * c, -1, tid);
}

// =============== main: mma.sync bf16-split chunked scan ===============
// 256 thr, grid 128. Per chunk: Y[i][h]=Tz*U+V*X (+Dv*u), S[n][h]=W^T*U, X+=S.
// Warp w: rb=w>>1 (16-row block), ch=w&1 (32-col half); does Y strip then S strip.
// bf16 tiles padded to 72 cols (144B rows). B operands stored k-contiguous.
__device__ __forceinline__ void mmab(float* c, const uint32_t a[4], const uint32_t b[2]) {
    asm volatile("mma.sync.aligned.m16n8k16.row.col.f32.bf16.bf16.f32 "
        "{%0,%1,%2,%3}, {%4,%5,%6,%7}, {%8,%9}, {%0,%1,%2,%3};"
        : "+f"(c[0]), "+f"(c[1]), "+f"(c[2]), "+f"(c[3])
        : "r"(a[0]), "r"(a[1]), "r"(a[2]), "r"(a[3]), "r"(b[0]), "r"(b[1]));
}
__device__ __forceinline__ void ldA(const char* A, int row, int kb, int lane, uint32_t a[4]) {
    int g = lane >> 2, c2 = (lane & 3) << 1;
    const char* p = A + (row + g) * 144 + (kb + c2) * 2;
    a[0] = *(const uint32_t*)p;
    a[2] = *(const uint32_t*)(p + 16);
    const char* q = p + 8 * 144;
    a[1] = *(const uint32_t*)q;
    a[3] = *(const uint32_t*)(q + 16);
}
__device__ __forceinline__ void ldB(const char* Bt, int ncol, int kb, int lane, uint32_t b[2]) {
    const char* p = Bt + (ncol + (lane >> 2)) * 144 + (kb + ((lane & 3) << 1)) * 2;
    b[0] = *(const uint32_t*)p;
    b[1] = *(const uint32_t*)(p + 16);
}

__global__ void __launch_bounds__(256, 1)
main_kernel(const float* __restrict__ u, const float* __restrict__ Dp, float* __restrict__ y) {
    extern __shared__ float sm[];
    char* smc = (char*)sm;
    char* Ahi  = smc;            // [128][72] bf16: rows 0-63 Tz[i][j], 64-127 WT[n][j]
    char* Alo  = smc + 18432;
    char* Vhi  = smc + 36864;    // [64][72]  V[i][n]
    char* Vlo  = smc + 46080;
    char* Uthi = smc + 55296;    // [64][72]  Ut[h][j]
    char* Utlo = smc + 64512;
    char* Xthi = smc + 73728;    // [64][72]  Xt[h][n]
    char* Xtlo = smc + 82944;
    float* Uf  = (float*)(smc + 92160);   // [64][68] fp32 u
    float* Xs  = (float*)(smc + 109568);  // [64][68] fp32 state X[n][h]

    int tid = threadIdx.x;
    int wid = tid >> 5, lane = tid & 31;
    int b = blockIdx.x >> 3;
    int habs = (blockIdx.x & 7) << 6;
    float Dv = Dp[0];
    const float* ub = u + (size_t)b * LSEQ * HD + habs;
    float* yb = y + (size_t)b * LSEQ * HD + habs;

    int rb16 = (wid >> 1) << 4;
    int ch32 = (wid & 1) << 5;
    int g = lane >> 2, n0 = (lane & 3) << 1;

    int jr = tid >> 2;            // staging: row 0..63
    int o0 = (tid & 3) << 4;      // staging: col base

    // ---- Tz precompute (Uf, Xs as scratch) ----
#pragma unroll
    for (int k = 0; k < 4; k++) {
        float4 w = __ldg((const float4*)(d_W + (size_t)jr * 64 + o0) + k);
        *(float4*)(Uf + jr * 68 + o0 + 4 * k) = w;        // Wf[j][n]
        float4 v = __ldg((const float4*)(d_V + (size_t)jr * 64 + o0) + k);
        const float* pv = (const float*)&v;
#pragma unroll
        for (int e = 0; e < 4; e++) Xs[(o0 + 4 * k + e) * 68 + jr] = pv[e];  // VT[n][i]
    }
    __syncthreads();
    {
        int jj = tid >> 2, i0 = (tid & 3) << 4;
        float ta[16];
#pragma unroll
        for (int q = 0; q < 16; q++) ta[q] = 0.f;
        for (int n = 0; n < 64; n++) {
            float w = Uf[jj * 68 + n];
            const float* vr = Xs + n * 68 + i0;
#pragma unroll
            for (int q = 0; q < 16; q += 4) {
                float4 v = *(const float4*)(vr + q);
                ta[q] = fmaf(w, v.x, ta[q]);
                ta[q + 1] = fmaf(w, v.y, ta[q + 1]);
                ta[q + 2] = fmaf(w, v.z, ta[q + 2]);
                ta[q + 3] = fmaf(w, v.w, ta[q + 3]);
            }
        }
        __syncthreads();
#pragma unroll
        for (int q = 0; q < 16; q++) {
            int i = i0 + q;
            float val = (jj <= i) ? ta[q] : 0.f;   // Tz[i][j], i >= j
            __nv_bfloat16 h, l; split2(val, h, l);
            *(__nv_bfloat16*)(Ahi + i * 144 + jj * 2) = h;
            *(__nv_bfloat16*)(Alo + i * 144 + jj * 2) = l;
        }
    }
    // zero X state + Xt tiles
    for (int f = tid; f < 4352; f += 256) Xs[f] = 0.f;
    for (int f = tid; f < 2304; f += 256) {
        ((uint32_t*)Xthi)[f] = 0u;
        ((uint32_t*)Xtlo)[f] = 0u;
    }
    // stage chunk 0
    float4 uu[4], ww[4], vv[4];
#pragma unroll
    for (int k = 0; k < 4; k++) {
        uu[k] = __ldg((const float4*)(ub + (size_t)jr * HD + o0) + k);
        ww[k] = __ldg((const float4*)(d_W + (size_t)jr * 64 + o0) + k);
        vv[k] = __ldg((const float4*)(d_V + (size_t)jr * 64 + o0) + k);
    }
#define STAGE_STS() do {                                                      \
    _Pragma("unroll")                                                         \
    for (int k = 0; k < 4; k++) {                                             \
        *(float4*)(Uf + jr * 68 + o0 + 4 * k) = uu[k];                        \
        const float* pu = (const float*)&uu[k];                               \
        const float* pw = (const float*)&ww[k];                               \
        const float* pv = (const float*)&vv[k];                               \
        _Pragma("unroll")                                                     \
        for (int e = 0; e < 4; e++) {                                         \
            int idx = o0 + 4 * k + e;                                         \
            __nv_bfloat16 h, l;                                               \
            split2(pu[e], h, l);                                              \
            *(__nv_bfloat16*)(Uthi + idx * 144 + jr * 2) = h;                 \
            *(__nv_bfloat16*)(Utlo + idx * 144 + jr * 2) = l;                 \
            split2(pw[e], h, l);                                              \
            *(__nv_bfloat16*)(Ahi + (64 + idx) * 144 + jr * 2) = h;           \
            *(__nv_bfloat16*)(Alo + (64 + idx) * 144 + jr * 2) = l;           \
        }                                                                     \
        _Pragma("unroll")                                                     \
        for (int e = 0; e < 4; e += 2) {                                      \
            __nv_bfloat16 h0, l0, h1, l1;                                     \
            split2(pv[e], h0, l0); split2(pv[e + 1], h1, l1);                 \
            int idx = o0 + 4 * k + e;                                         \
            ushort2 ph; ph.x = *(unsigned short*)&h0; ph.y = *(unsigned short*)&h1; \
            *(ushort2*)(Vhi + jr * 144 + idx * 2) = ph;                       \
            ushort2 pl; pl.x = *(unsigned short*)&l0; pl.y = *(unsigned short*)&l1; \
            *(ushort2*)(Vlo + jr * 144 + idx * 2) = pl;                       \
        }                                                                     \
    }                                                                         \
} while (0)
    STAGE_STS();
    __syncthreads();

    for (int c = 0; c < 32; c++) {
        int tb = c << 6;
        if (c < 31) {
            int tbn = tb + 64;
#pragma unroll
            for (int k = 0; k < 4; k++) {
                uu[k] = __ldg((const float4*)(ub + (size_t)(tbn + jr) * HD + o0) + k);
                ww[k] = __ldg((const float4*)(d_W + (size_t)(tbn + jr) * 64 + o0) + k);
                vv[k] = __ldg((const float4*)(d_V + (size_t)(tbn + jr) * 64 + o0) + k);
            }
        }
        // ---- Y strip: acc = Tz*U + V*X (3 split passes) ----
        float acc[4][4];
#pragma unroll
        for (int t = 0; t < 4; t++)
#pragma unroll
            for (int q = 0; q < 4; q++) acc[t][q] = 0.f;
#pragma unroll
        for (int pass = 0; pass < 3; pass++) {
            const char* Asrc = (pass == 2) ? Alo : Ahi;
            const char* Vs   = (pass == 2) ? Vlo : Vhi;
            const char* Bu   = (pass == 1) ? Utlo : Uthi;
            const char* Bx   = (pass == 1) ? Xtlo : Xthi;
#pragma unroll
            for (int k4 = 0; k4 < 4; k4++) {
                uint32_t a[4], bfr[2];
                ldA(Asrc, rb16, k4 * 16, lane, a);
#pragma unroll
                for (int t = 0; t < 4; t++) {
                    ldB(Bu, ch32 + t * 8, k4 * 16, lane, bfr);
                    mmab(acc[t], a, bfr);
                }
                ldA(Vs, rb16, k4 * 16, lane, a);
#pragma unroll
                for (int t = 0; t < 4; t++) {
                    ldB(Bx, ch32 + t * 8, k4 * 16, lane, bfr);
                    mmab(acc[t], a, bfr);
                }
            }
        }
        // Y epilogue: + Dv*u, store
#pragma unroll
        for (int t = 0; t < 4; t++) {
            int col = ch32 + t * 8 + n0;
            int r0 = rb16 + g;
            float2 u0 = *(const float2*)(Uf + r0 * 68 + col);
            float2 o0v; o0v.x = acc[t][0] + Dv * u0.x; o0v.y = acc[t][1] + Dv * u0.y;
            *(float2*)(yb + (size_t)(tb + r0) * HD + col) = o0v;
            float2 u1 = *(const float2*)(Uf + (r0 + 8) * 68 + col);
            float2 o1v; o1v.x = acc[t][2] + Dv * u1.x; o1v.y = acc[t][3] + Dv * u1.y;
            *(float2*)(yb + (size_t)(tb + r0 + 8) * HD + col) = o1v;
        }
        // ---- S strip: acc = W^T*U ----
#pragma unroll
        for (int t = 0; t < 4; t++)
#pragma unroll
            for (int q = 0; q < 4; q++) acc[t][q] = 0.f;
#pragma unroll
        for (int pass = 0; pass < 3; pass++) {
            const char* Asrc = (pass == 2) ? Alo : Ahi;
            const char* Bu   = (pass == 1) ? Utlo : Uthi;
#pragma unroll
            for (int k4 = 0; k4 < 4; k4++) {
                uint32_t a[4], bfr[2];
                ldA(Asrc, 64 + rb16, k4 * 16, lane, a);
#pragma unroll
                for (int t = 0; t < 4; t++) {
                    ldB(Bu, ch32 + t * 8, k4 * 16, lane, bfr);
                    mmab(acc[t], a, bfr);
                }
            }
        }
        // X state RMW (exclusive per-warp elements); keep new vals in acc
#pragma unroll
        for (int t = 0; t < 4; t++) {
            int col = ch32 + t * 8 + n0;
            int nr = rb16 + g;
            float2 xv = *(const float2*)(Xs + nr * 68 + col);
            xv.x += acc[t][0]; xv.y += acc[t][1];
            *(float2*)(Xs + nr * 68 + col) = xv;
            acc[t][0] = xv.x; acc[t][1] = xv.y;
            float2 xw = *(const float2*)(Xs + (nr + 8) * 68 + col);
            xw.x += acc[t][2]; xw.y += acc[t][3];
            *(float2*)(Xs + (nr + 8) * 68 + col) = xw;
            acc[t][2] = xw.x; acc[t][3] = xw.y;
        }
        __syncthreads();   // all reads of Xt/Ut/A/V/Uf done; Xs updated

        if (c < 31) {
            // re-emit X^T bf16 split (Xt[h=col][n])
#pragma unroll
            for (int t = 0; t < 4; t++) {
                int col = ch32 + t * 8 + n0;
                int nr = rb16 + g;
                __nv_bfloat16 h, l;
                split2(acc[t][0], h, l);
                *(__nv_bfloat16*)(Xthi + col * 144 + nr * 2) = h;
                *(__nv_bfloat16*)(Xtlo + col * 144 + nr * 2) = l;
                split2(acc[t][1], h, l);
                *(__nv_bfloat16*)(Xthi + (col + 1) * 144 + nr * 2) = h;
                *(__nv_bfloat16*)(Xtlo + (col + 1) * 144 + nr * 2) = l;
                split2(acc[t][2], h, l);
                *(__nv_bfloat16*)(Xthi + col * 144 + (nr + 8) * 2) = h;
                *(__nv_bfloat16*)(Xtlo + col * 144 + (nr + 8) * 2) = l;
                split2(acc[t][3], h, l);
                *(__nv_bfloat16*)(Xthi + (col + 1) * 144 + (nr + 8) * 2) = h;
                *(__nv_bfloat16*)(Xtlo + (col + 1) * 144 + (nr + 8) * 2) = l;
            }
            STAGE_STS();
            __syncthreads();   // new tiles + Xt visible
        }
    }
}

extern "C" void kernel_launch(void* const* d_in, const int* in_sizes, int n_in,
                              void* d_out, int out_size) {
    const float* u = (const float*)d_in[0];
    const float* B_ssm = (const float*)d_in[1];
    const float* C_ssm = (const float*)d_in[2];
    const float* D_skip = (const float*)d_in[3];
    const float* log_dt = (const float*)d_in[4];
    float* y = (float*)d_out;

    cudaFuncSetAttribute(setup_kernel, cudaFuncAttributeMaxDynamicSharedMemorySize, 114688);
    cudaFuncSetAttribute(chunk_kernel, cudaFuncAttributeMaxDynamicSharedMemorySize, 98304);
    cudaFuncSetAttribute(main_kernel,  cudaFuncAttributeMaxDynamicSharedMemorySize, 131072);

    setup_kernel<<<1, 256, 114688>>>(B_ssm, log_dt);
    stageA_kernel<<<2, 256>>>(C_ssm);
    chunk_kernel<<<32, 256, 98304>>>();
    main_kernel<<<BSZ * 8, 256, 131072>>>(u, D_skip, y);
}

// round 17
// speedup vs baseline: 1.8703x; 1.0091x over previous
#include <cuda_runtime.h>
#include <cuda_bf16.h>
#include <math.h>
#include <stdint.h>

#define LSEQ 2048
#define HD   512
#define BSZ  16

__device__ __align__(16) float d_P [11 * 4096];
__device__ __align__(16) float d_PT[11 * 4096];
__device__ __align__(16) float d_Bbar[64];
__device__ __align__(16) float d_W0 [64 * 64];
__device__ __align__(16) float d_Vr0[64 * 64];
__device__ __align__(16) float d_W[LSEQ * 64];
__device__ __align__(16) float d_V[LSEQ * 64];
__device__ __align__(16) __nv_bfloat16 d_WTh[LSEQ * 64];  // [c][n][j]
__device__ __align__(16) __nv_bfloat16 d_WTl[LSEQ * 64];
__device__ __align__(16) __nv_bfloat16 d_Vh [LSEQ * 64];  // [c][i][n]
__device__ __align__(16) __nv_bfloat16 d_Vl [LSEQ * 64];

__device__ __forceinline__ uint64_t dup2(float x) {
    uint64_t r; uint32_t u = __float_as_uint(x);
    asm("mov.b64 %0, {%1, %1};" : "=l"(r) : "r"(u));
    return r;
}
__device__ __forceinline__ void fma2(uint64_t& d, uint64_t a, uint64_t b) {
    asm("fma.rn.f32x2 %0, %1, %2, %0;" : "+l"(d) : "l"(a), "l"(b));
}
__device__ __forceinline__ float2 un2(uint64_t v) {
    float2 r;
    asm("mov.b64 {%0, %1}, %2;" : "=f"(r.x), "=f"(r.y) : "l"(v));
    return r;
}
__device__ __forceinline__ void split2(float x, __nv_bfloat16& h, __nv_bfloat16& l) {
    h = __float2bfloat16(x);
    l = __float2bfloat16(x - __bfloat162float(h));
}

// =============== setup (R13, proven, frozen) ===============
__device__ __forceinline__ void mm64T(const float* __restrict__ AT, const float* __restrict__ B,
                                      float* __restrict__ C, float* __restrict__ CT,
                                      int tid, int mode, float scale) {
    int tx = tid & 15, ty = tid >> 4;
    int j0 = tx << 2, i0 = ty << 2;
    uint64_t acc[4][2];
#pragma unroll
    for (int a = 0; a < 4; a++) { acc[a][0] = 0ull; acc[a][1] = 0ull; }
#pragma unroll 8
    for (int k = 0; k < 64; k++) {
        float4 av = *(const float4*)(AT + k * 64 + i0);
        ulonglong2 bv = *(const ulonglong2*)(B + k * 64 + j0);
#pragma unroll
        for (int a = 0; a < 4; a++) {
            uint64_t ad = dup2((&av.x)[a]);
            fma2(acc[a][0], ad, bv.x);
            fma2(acc[a][1], ad, bv.y);
        }
    }
    float o[4][4];
#pragma unroll
    for (int a = 0; a < 4; a++) {
        float2 p0 = un2(acc[a][0]);
        float2 p1 = un2(acc[a][1]);
        o[a][0] = p0.x; o[a][1] = p0.y; o[a][2] = p1.x; o[a][3] = p1.y;
        if (mode == 1) {
#pragma unroll
            for (int q = 0; q < 4; q++)
                o[a][q] = o[a][q] * scale + ((i0 + a) == (j0 + q) ? 1.f : 0.f);
        }
        float4 ov; ov.x = o[a][0]; ov.y = o[a][1]; ov.z = o[a][2]; ov.w = o[a][3];
        *(float4*)(C + (i0 + a) * 64 + j0) = ov;
    }
#pragma unroll
    for (int q = 0; q < 4; q++) {
        float4 ov; ov.x = o[0][q]; ov.y = o[1][q]; ov.z = o[2][q]; ov.w = o[3][q];
        *(float4*)(CT + (j0 + q) * 64 + i0) = ov;
    }
}

__global__ void __launch_bounds__(256, 1)
setup_kernel(const float* __restrict__ B_in, const float* __restrict__ logdt) {
    extern __shared__ float sm[];
    float* As = sm;
    float* Xs = sm + 4096;
    float* XsT = sm + 8192;
    float* R0 = sm + 12288;
    float* R0T = sm + 16384;
    float* R1 = sm + 20480;
    float* R1T = sm + 24576;
    __shared__ float colsum[64], rhs[64], bbsh[64], bsh[64];
    __shared__ int s_sh;
    int tid = threadIdx.x;
    double dt = exp((double)logdt[0]);
    for (int e = tid; e < 4096; e += 256) {
        int i = e >> 6, j = e & 63;
        float a = 0.f, x = 0.f;
        if (j <= i) {
            double pij = sqrt((1.0 + 2.0 * i) * (1.0 + 2.0 * j));
            double av = pij - (i == j ? (double)i : 0.0);
            a = (float)(-av); x = (float)(-av * dt);
        }
        As[e] = a; Xs[e] = x; XsT[(j << 6) + i] = x;
    }
    if (tid < 64) bsh[tid] = B_in[tid];
    __syncthreads();
    if (tid < 64) {
        float ssum = 0.f;
        for (int i = tid; i < 64; i++) ssum += fabsf(Xs[i * 64 + tid]);
        colsum[tid] = ssum;
    }
    __syncthreads();
    if (tid == 0) {
        float mx = 0.f;
        for (int j = 0; j < 64; j++) mx = fmaxf(mx, colsum[j]);
        int s = 0; float v = mx;
        while (v > 2.0f && s < 30) { v *= 0.5f; s++; }
        s_sh = s;
    }
    __syncthreads();
    int s = s_sh;
    float scale = ldexpf(1.0f, -s);
    for (int e = tid; e < 4096; e += 256) { Xs[e] *= scale; XsT[e] *= scale; }
    __syncthreads();
    for (int e = tid; e < 4096; e += 256) {
        int i = e >> 6, j = e & 63;
        float d = (i == j) ? 1.f : 0.f;
        R0[e] = Xs[e] * (1.f / 12.f) + d;
        R0T[e] = XsT[e] * (1.f / 12.f) + d;
    }
    __syncthreads();
    float *cur = R0, *curT = R0T, *nxt = R1, *nxtT = R1T;
    for (int k = 11; k >= 1; k--) {
        mm64T(XsT, cur, nxt, nxtT, tid, 1, 1.f / (float)k);
        __syncthreads();
        float* t;
        t = cur; cur = nxt; nxt = t;
        t = curT; curT = nxtT; nxtT = t;
    }
    for (int q = 0; q < s; q++) {
        mm64T(curT, cur, nxt, nxtT, tid, 0, 0.f);
        __syncthreads();
        float* t;
        t = cur; cur = nxt; nxt = t;
        t = curT; curT = nxtT; nxtT = t;
    }
    if (tid < 64) {
        float acc = 0.f;
        for (int j = 0; j < 64; j++) {
            float p = cur[tid * 64 + j] - (tid == j ? 1.f : 0.f);
            acc = fmaf(p, bsh[j], acc);
        }
        rhs[tid] = acc;
    }
    __syncthreads();
    for (int e = tid; e < 4096; e += 256) { d_P[e] = cur[e]; d_PT[e] = curT[e]; }
    for (int k = 1; k < 11; k++) {
        mm64T(curT, cur, nxt, nxtT, tid, 0, 0.f);
        __syncthreads();
        for (int e = tid; e < 4096; e += 256) {
            d_P[k * 4096 + e] = nxt[e];
            d_PT[k * 4096 + e] = nxtT[e];
        }
        float* t;
        t = cur; cur = nxt; nxt = t;
        t = curT; curT = nxtT; nxtT = t;
        __syncthreads();
    }
    float accv = (tid < 64) ? rhs[tid] : 0.f;
    for (int j = 0; j < 64; j++) {
        if (tid == j) bbsh[j] = accv / As[j * 64 + j];
        __syncthreads();
        if (tid < 64 && tid > j) accv = fmaf(-As[tid * 64 + j], bbsh[j], accv);
        __syncthreads();
    }
    if (tid < 64) d_Bbar[tid] = bbsh[tid];
}

__global__ void __launch_bounds__(256, 1)
stageA_kernel(const float* __restrict__ C_in) {
    __shared__ float M[4096];
    __shared__ float Pb[4096];
    int tid = threadIdx.x;
    int isW = (blockIdx.x == 0);
    if (tid < 64) M[tid] = isW ? d_Bbar[tid] : C_in[tid];
    for (int k = 0; k < 6; k++) {
        const float* src = (isW ? d_PT : d_P) + k * 4096;
        __syncthreads();
        for (int f = tid; f < 1024; f += 256)
            ((float4*)Pb)[f] = __ldg((const float4*)src + f);
        __syncthreads();
        int half = 1 << k;
        for (int idx = tid; idx < half * 16; idx += 256) {
            int row = idx >> 4, n0 = (idx & 15) << 2;
            float4 acc = make_float4(0.f, 0.f, 0.f, 0.f);
            for (int m = 0; m < 64; m++) {
                float w = M[row * 64 + m];
                float4 p = *(const float4*)(Pb + m * 64 + n0);
                acc.x = fmaf(w, p.x, acc.x);
                acc.y = fmaf(w, p.y, acc.y);
                acc.z = fmaf(w, p.z, acc.z);
                acc.w = fmaf(w, p.w, acc.w);
            }
            *(float4*)(M + (half + row) * 64 + n0) = acc;
        }
    }
    __syncthreads();
    float* dst = isW ? d_W0 : d_Vr0;
    for (int f = tid; f < 1024; f += 256) ((float4*)dst)[f] = ((const float4*)M)[f];
}

__device__ __forceinline__ void mmg(const float* __restrict__ A, const float* __restrict__ B,
                                    float* __restrict__ out, int row0, int rowstep, int tid) {
    int tx = tid & 15, ty = tid >> 4;
    int j0 = tx << 2, i0 = ty << 2;
    float acc[4][4];
#pragma unroll
    for (int a = 0; a < 4; a++)
#pragma unroll
        for (int q = 0; q < 4; q++) acc[a][q] = 0.f;
#pragma unroll 8
    for (int k = 0; k < 64; k++) {
        float a0 = A[(i0 + 0) * 64 + k];
        float a1 = A[(i0 + 1) * 64 + k];
        float a2 = A[(i0 + 2) * 64 + k];
        float a3 = A[(i0 + 3) * 64 + k];
        float4 bv = *(const float4*)(B + k * 64 + j0);
        acc[0][0] = fmaf(a0, bv.x, acc[0][0]); acc[0][1] = fmaf(a0, bv.y, acc[0][1]);
        acc[0][2] = fmaf(a0, bv.z, acc[0][2]); acc[0][3] = fmaf(a0, bv.w, acc[0][3]);
        acc[1][0] = fmaf(a1, bv.x, acc[1][0]); acc[1][1] = fmaf(a1, bv.y, acc[1][1]);
        acc[1][2] = fmaf(a1, bv.z, acc[1][2]); acc[1][3] = fmaf(a1, bv.w, acc[1][3]);
        acc[2][0] = fmaf(a2, bv.x, acc[2][0]); acc[2][1] = fmaf(a2, bv.y, acc[2][1]);
        acc[2][2] = fmaf(a2, bv.z, acc[2][2]); acc[2][3] = fmaf(a2, bv.w, acc[2][3]);
        acc[3][0] = fmaf(a3, bv.x, acc[3][0]); acc[3][1] = fmaf(a3, bv.y, acc[3][1]);
        acc[3][2] = fmaf(a3, bv.z, acc[3][2]); acc[3][3] = fmaf(a3, bv.w, acc[3][3]);
    }
#pragma unroll
    for (int a = 0; a < 4; a++) {
        float4 o; o.x = acc[a][0]; o.y = acc[a][1]; o.z = acc[a][2]; o.w = acc[a][3];
        *(float4*)(out + (size_t)(row0 + rowstep * (i0 + a)) * 64 + j0) = o;
    }
}

__global__ void __launch_bounds__(256, 1)
chunk_kernel() {
    extern __shared__ float cs[];
    float* W0s = cs;
    float* Vr0s = cs + 4096;
    float* Qa = cs + 8192;
    float* Qb = cs + 12288;
    float* QT = cs + 16384;
    float* Pb = cs + 20480;
    int tid = threadIdx.x;
    int c = blockIdx.x;
    for (int f = tid; f < 1024; f += 256) {
        ((float4*)W0s)[f] = __ldg((const float4*)d_W0 + f);
        ((float4*)Vr0s)[f] = __ldg((const float4*)d_Vr0 + f);
    }
    __syncthreads();
    if (c == 0) {
        for (int f = tid; f < 1024; f += 256) ((float4*)d_W)[f] = ((const float4*)W0s)[f];
        for (int e = tid; e < 4096; e += 256) {
            int r = e >> 6, n = e & 63;
            d_V[(size_t)(2047 - r) * 64 + n] = Vr0s[e];
        }
        return;
    }
    int bits = c;
    int k0 = __ffs(bits) - 1; bits &= bits - 1;
    for (int f = tid; f < 1024; f += 256)
        ((float4*)Qa)[f] = __ldg((const float4*)(d_P + (6 + k0) * 4096) + f);
    float *qcur = Qa, *qnxt = Qb;
    while (bits) {
        int k = __ffs(bits) - 1; bits &= bits - 1;
        __syncthreads();
        for (int f = tid; f < 1024; f += 256)
            ((float4*)Pb)[f] = __ldg((const float4*)(d_P + (6 + k) * 4096) + f);
        __syncthreads();
        mmg(qcur, Pb, qnxt, 0, 1, tid);
        float* t = qcur; qcur = qnxt; qnxt = t;
    }
    __syncthreads();
    for (int e = tid; e < 4096; e += 256) {
        int i = e >> 6, j = e & 63;
        QT[j * 64 + i] = qcur[e];
    }
    __syncthreads();
    mmg(W0s, QT, d_W, 64 * c, 1, tid);
    mmg(Vr0s, qcur, d_V, 2047 - 64 * c, -1, tid);
}

// ========= split kernel: precompute bf16 hi/lo tiles of W (transposed) and V =========
__global__ void __launch_bounds__(256, 1)
split_kernel() {
    __shared__ float Wt[4096];
    int c = blockIdx.x, tid = threadIdx.x;
    for (int f = tid; f < 1024; f += 256)
        ((float4*)Wt)[f] = __ldg((const float4*)(d_W + (size_t)c * 4096) + f);
    __syncthreads();
    // WT[n][j] pairs along j
    for (int e = tid; e < 2048; e += 256) {
        int n = e >> 5, jp = e & 31;
        __nv_bfloat16 h0, l0, h1, l1;
        split2(Wt[(jp * 2) * 64 + n], h0, l0);
        split2(Wt[(jp * 2 + 1) * 64 + n], h1, l1);
        ushort2 ph; ph.x = *(unsigned short*)&h0; ph.y = *(unsigned short*)&h1;
        ushort2 pl; pl.x = *(unsigned short*)&l0; pl.y = *(unsigned short*)&l1;
        ((ushort2*)d_WTh)[(size_t)c * 2048 + n * 32 + jp] = ph;
        ((ushort2*)d_WTl)[(size_t)c * 2048 + n * 32 + jp] = pl;
    }
    // V[i][n] elementwise pairs
    for (int e = tid; e < 2048; e += 256) {
        float2 v = ((const float2*)(d_V + (size_t)c * 4096))[e];
        __nv_bfloat16 h0, l0, h1, l1;
        split2(v.x, h0, l0); split2(v.y, h1, l1);
        ushort2 ph; ph.x = *(unsigned short*)&h0; ph.y = *(unsigned short*)&h1;
        ushort2 pl; pl.x = *(unsigned short*)&l0; pl.y = *(unsigned short*)&l1;
        ((ushort2*)d_Vh)[(size_t)c * 2048 + e] = ph;
        ((ushort2*)d_Vl)[(size_t)c * 2048 + e] = pl;
    }
}

// =============== main: mma.sync bf16-split, 512 threads, 16x16 warp tiles ===============
__device__ __forceinline__ void mmab(float* c, const uint32_t a[4], const uint32_t b[2]) {
    asm volatile("mma.sync.aligned.m16n8k16.row.col.f32.bf16.bf16.f32 "
        "{%0,%1,%2,%3}, {%4,%5,%6,%7}, {%8,%9}, {%0,%1,%2,%3};"
        : "+f"(c[0]), "+f"(c[1]), "+f"(c[2]), "+f"(c[3])
        : "r"(a[0]), "r"(a[1]), "r"(a[2]), "r"(a[3]), "r"(b[0]), "r"(b[1]));
}
__device__ __forceinline__ void ldA(const char* A, int row, int kb, int lane, uint32_t a[4]) {
    int g = lane >> 2, c2 = (lane & 3) << 1;
    const char* p = A + (row + g) * 144 + (kb + c2) * 2;
    a[0] = *(const uint32_t*)p;
    a[2] = *(const uint32_t*)(p + 16);
    const char* q = p + 8 * 144;
    a[1] = *(const uint32_t*)q;
    a[3] = *(const uint32_t*)(q + 16);
}
__device__ __forceinline__ void ldB(const char* Bt, int ncol, int kb, int lane, uint32_t b[2]) {
    const char* p = Bt + (ncol + (lane >> 2)) * 144 + (kb + ((lane & 3) << 1)) * 2;
    b[0] = *(const uint32_t*)p;
    b[1] = *(const uint32_t*)(p + 16);
}

__global__ void __launch_bounds__(512, 1)
main_kernel(const float* __restrict__ u, const float* __restrict__ Dp, float* __restrict__ y) {
    extern __shared__ float sm[];
    char* smc = (char*)sm;
    char* Ahi  = smc;            // [128][72] bf16: rows 0-63 Tz[i][j], 64-127 WT[n][j]
    char* Alo  = smc + 18432;
    char* Vhi  = smc + 36864;    // [64][72]  V[i][n]
    char* Vlo  = smc + 46080;
    char* Uthi = smc + 55296;    // [64][72]  Ut[h][j]
    char* Utlo = smc + 64512;
    char* Xthi = smc + 73728;    // [64][72]  Xt[h][n]
    char* Xtlo = smc + 82944;
    float* Uf  = (float*)(smc + 92160);   // [64][68] fp32 u
    float* Xs  = (float*)(smc + 109568);  // [64][68] fp32 X[n][h]

    int tid = threadIdx.x;
    int wid = tid >> 5, lane = tid & 31;
    int b = blockIdx.x >> 3;
    int habs = (blockIdx.x & 7) << 6;
    float Dv = Dp[0];
    const float* ub = u + (size_t)b * LSEQ * HD + habs;
    float* yb = y + (size_t)b * LSEQ * HD + habs;

    int rb16 = (wid >> 2) << 4;     // 0,16,32,48
    int ch16 = (wid & 3) << 4;      // 0,16,32,48
    int g = lane >> 2, n0 = (lane & 3) << 1;

    int jr = tid >> 3;              // staging row 0..63
    int o0 = (tid & 7) << 3;        // staging col base (8 elems)
    int crow = tid >> 3, cseg = tid & 7;   // uint4 copy coords

    // ---- Tz precompute (Uf, Xs as scratch) ----
#pragma unroll
    for (int k = 0; k < 2; k++) {
        float4 w = __ldg((const float4*)(d_W + (size_t)jr * 64 + o0) + k);
        *(float4*)(Uf + jr * 68 + o0 + 4 * k) = w;        // Wf[j][n]
        float4 v = __ldg((const float4*)(d_V + (size_t)jr * 64 + o0) + k);
        const float* pv = (const float*)&v;
#pragma unroll
        for (int e = 0; e < 4; e++) Xs[(o0 + 4 * k + e) * 68 + jr] = pv[e];  // VT[n][i]
    }
    __syncthreads();
    {
        int jj = tid >> 3, i0 = (tid & 7) << 3;
        float ta[8];
#pragma unroll
        for (int q = 0; q < 8; q++) ta[q] = 0.f;
        for (int n = 0; n < 64; n++) {
            float w = Uf[jj * 68 + n];
            const float* vr = Xs + n * 68 + i0;
#pragma unroll
            for (int q = 0; q < 8; q += 4) {
                float4 v = *(const float4*)(vr + q);
                ta[q] = fmaf(w, v.x, ta[q]);
                ta[q + 1] = fmaf(w, v.y, ta[q + 1]);
                ta[q + 2] = fmaf(w, v.z, ta[q + 2]);
                ta[q + 3] = fmaf(w, v.w, ta[q + 3]);
            }
        }
        __syncthreads();
#pragma unroll
        for (int q = 0; q < 8; q++) {
            int i = i0 + q;
            float val = (jj <= i) ? ta[q] : 0.f;
            __nv_bfloat16 h, l; split2(val, h, l);
            *(__nv_bfloat16*)(Ahi + i * 144 + jj * 2) = h;
            *(__nv_bfloat16*)(Alo + i * 144 + jj * 2) = l;
        }
    }
    for (int f = tid; f < 4352; f += 512) Xs[f] = 0.f;
    for (int f = tid; f < 4608; f += 512) {
        ((uint32_t*)Xthi)[f] = 0u;
        ((uint32_t*)Xtlo)[f] = 0u;
    }
    // stage chunk 0
    float4 uu0, uu1;
    uint4 wth, wtl, vh4, vl4;
    uu0 = __ldg((const float4*)(ub + (size_t)jr * HD + o0));
    uu1 = __ldg((const float4*)(ub + (size_t)jr * HD + o0) + 1);
    wth = __ldg((const uint4*)d_WTh + tid);
    wtl = __ldg((const uint4*)d_WTl + tid);
    vh4 = __ldg((const uint4*)d_Vh + tid);
    vl4 = __ldg((const uint4*)d_Vl + tid);
#define STAGE_STS() do {                                                      \
    *(float4*)(Uf + jr * 68 + o0) = uu0;                                      \
    *(float4*)(Uf + jr * 68 + o0 + 4) = uu1;                                  \
    const float* pu0 = (const float*)&uu0;                                    \
    const float* pu1 = (const float*)&uu1;                                    \
    _Pragma("unroll")                                                         \
    for (int e = 0; e < 4; e++) {                                             \
        __nv_bfloat16 h, l;                                                   \
        split2(pu0[e], h, l);                                                 \
        *(__nv_bfloat16*)(Uthi + (o0 + e) * 144 + jr * 2) = h;                \
        *(__nv_bfloat16*)(Utlo + (o0 + e) * 144 + jr * 2) = l;                \
        split2(pu1[e], h, l);                                                 \
        *(__nv_bfloat16*)(Uthi + (o0 + 4 + e) * 144 + jr * 2) = h;            \
        *(__nv_bfloat16*)(Utlo + (o0 + 4 + e) * 144 + jr * 2) = l;            \
    }                                                                         \
    *(uint4*)(Ahi + (64 + crow) * 144 + cseg * 16) = wth;                     \
    *(uint4*)(Alo + (64 + crow) * 144 + cseg * 16) = wtl;                     \
    *(uint4*)(Vhi + crow * 144 + cseg * 16) = vh4;                            \
    *(uint4*)(Vlo + crow * 144 + cseg * 16) = vl4;                            \
} while (0)
    STAGE_STS();
    __syncthreads();

    for (int c = 0; c < 32; c++) {
        int tb = c << 6;
        if (c < 31) {
            int tbn = tb + 64;
            uu0 = __ldg((const float4*)(ub + (size_t)(tbn + jr) * HD + o0));
            uu1 = __ldg((const float4*)(ub + (size_t)(tbn + jr) * HD + o0) + 1);
            wth = __ldg((const uint4*)d_WTh + (c + 1) * 512 + tid);
            wtl = __ldg((const uint4*)d_WTl + (c + 1) * 512 + tid);
            vh4 = __ldg((const uint4*)d_Vh + (c + 1) * 512 + tid);
            vl4 = __ldg((const uint4*)d_Vl + (c + 1) * 512 + tid);
        }
        // ---- Y strip: acc = Tz*U + V*X ----
        float acc[2][4];
#pragma unroll
        for (int t = 0; t < 2; t++)
#pragma unroll
            for (int q = 0; q < 4; q++) acc[t][q] = 0.f;
#pragma unroll
        for (int pass = 0; pass < 3; pass++) {
            const char* Asrc = (pass == 2) ? Alo : Ahi;
            const char* Vs   = (pass == 2) ? Vlo : Vhi;
            const char* Bu   = (pass == 1) ? Utlo : Uthi;
            const char* Bx   = (pass == 1) ? Xtlo : Xthi;
#pragma unroll
            for (int k4 = 0; k4 < 4; k4++) {
                uint32_t a[4], bfr[2];
                ldA(Asrc, rb16, k4 * 16, lane, a);
#pragma unroll
                for (int t = 0; t < 2; t++) {
                    ldB(Bu, ch16 + t * 8, k4 * 16, lane, bfr);
                    mmab(acc[t], a, bfr);
                }
                ldA(Vs, rb16, k4 * 16, lane, a);
#pragma unroll
                for (int t = 0; t < 2; t++) {
                    ldB(Bx, ch16 + t * 8, k4 * 16, lane, bfr);
                    mmab(acc[t], a, bfr);
                }
            }
        }
#pragma unroll
        for (int t = 0; t < 2; t++) {
            int col = ch16 + t * 8 + n0;
            int r0 = rb16 + g;
            float2 u0v = *(const float2*)(Uf + r0 * 68 + col);
            float2 o0v; o0v.x = acc[t][0] + Dv * u0v.x; o0v.y = acc[t][1] + Dv * u0v.y;
            *(float2*)(yb + (size_t)(tb + r0) * HD + col) = o0v;
            float2 u1v = *(const float2*)(Uf + (r0 + 8) * 68 + col);
            float2 o1v; o1v.x = acc[t][2] + Dv * u1v.x; o1v.y = acc[t][3] + Dv * u1v.y;
            *(float2*)(yb + (size_t)(tb + r0 + 8) * HD + col) = o1v;
        }
        // ---- S strip: acc = W^T*U ----
#pragma unroll
        for (int t = 0; t < 2; t++)
#pragma unroll
            for (int q = 0; q < 4; q++) acc[t][q] = 0.f;
#pragma unroll
        for (int pass = 0; pass < 3; pass++) {
            const char* Asrc = (pass == 2) ? Alo : Ahi;
            const char* Bu   = (pass == 1) ? Utlo : Uthi;
#pragma unroll
            for (int k4 = 0; k4 < 4; k4++) {
                uint32_t a[4], bfr[2];
                ldA(Asrc, 64 + rb16, k4 * 16, lane, a);
#pragma unroll
                for (int t = 0; t < 2; t++) {
                    ldB(Bu, ch16 + t * 8, k4 * 16, lane, bfr);
                    mmab(acc[t], a, bfr);
                }
            }
        }
        // X state RMW (exclusive per warp-tile)
#pragma unroll
        for (int t = 0; t < 2; t++) {
            int col = ch16 + t * 8 + n0;
            int nr = rb16 + g;
            float2 xv = *(const float2*)(Xs + nr * 68 + col);
            xv.x += acc[t][0]; xv.y += acc[t][1];
            *(float2*)(Xs + nr * 68 + col) = xv;
            acc[t][0] = xv.x; acc[t][1] = xv.y;
            float2 xw = *(const float2*)(Xs + (nr + 8) * 68 + col);
            xw.x += acc[t][2]; xw.y += acc[t][3];
            *(float2*)(Xs + (nr + 8) * 68 + col) = xw;
            acc[t][2] = xw.x; acc[t][3] = xw.y;
        }
        __syncthreads();   // all tile reads done; Xs updated

        if (c < 31) {
#pragma unroll
            for (int t = 0; t < 2; t++) {
                int col = ch16 + t * 8 + n0;
                int nr = rb16 + g;
                __nv_bfloat16 h, l;
                split2(acc[t][0], h, l);
                *(__nv_bfloat16*)(Xthi + col * 144 + nr * 2) = h;
                *(__nv_bfloat16*)(Xtlo + col * 144 + nr * 2) = l;
                split2(acc[t][1], h, l);
                *(__nv_bfloat16*)(Xthi + (col + 1) * 144 + nr * 2) = h;
                *(__nv_bfloat16*)(Xtlo + (col + 1) * 144 + nr * 2) = l;
                split2(acc[t][2], h, l);
                *(__nv_bfloat16*)(Xthi + col * 144 + (nr + 8) * 2) = h;
                *(__nv_bfloat16*)(Xtlo + col * 144 + (nr + 8) * 2) = l;
                split2(acc[t][3], h, l);
                *(__nv_bfloat16*)(Xthi + (col + 1) * 144 + (nr + 8) * 2) = h;
                *(__nv_bfloat16*)(Xtlo + (col + 1) * 144 + (nr + 8) * 2) = l;
            }
            STAGE_STS();
            __syncthreads();
        }
    }
}

extern "C" void kernel_launch(void* const* d_in, const int* in_sizes, int n_in,
                              void* d_out, int out_size) {
    const float* u = (const float*)d_in[0];
    const float* B_ssm = (const float*)d_in[1];
    const float* C_ssm = (const float*)d_in[2];
    const float* D_skip = (const float*)d_in[3];
    const float* log_dt = (const float*)d_in[4];
    float* y = (float*)d_out;

    cudaFuncSetAttribute(setup_kernel, cudaFuncAttributeMaxDynamicSharedMemorySize, 114688);
    cudaFuncSetAttribute(chunk_kernel, cudaFuncAttributeMaxDynamicSharedMemorySize, 98304);
    cudaFuncSetAttribute(main_kernel,  cudaFuncAttributeMaxDynamicSharedMemorySize, 131072);

    setup_kernel<<<1, 256, 114688>>>(B_ssm, log_dt);
    stageA_kernel<<<2, 256>>>(C_ssm);
    chunk_kernel<<<32, 256, 98304>>>();
    split_kernel<<<32, 256>>>();
    main_kernel<<<BSZ * 8, 512, 131072>>>(u, D_skip, y);
}